// round 11
// baseline (speedup 1.0000x reference)
#include <cuda_runtime.h>
#include <cuda_fp16.h>
#include <math.h>
#include <stdint.h>

// ---------------------------------------------------------------------------
// Problem constants
// ---------------------------------------------------------------------------
#define BATCH 4
#define SEQ 4096
#define DIM 1024
#define NHEAD 16
#define HDIM 64
#define M_ROWS (BATCH * SEQ)      // 16384
#define QKV_COLS (3 * DIM)        // 3072
#define NCHUNK 8
#define CHUNK_ROWS (SEQ / NCHUNK) // 512

// Scratch (device globals; allocation-free contract)
__device__ __half g_qkvh[(size_t)M_ROWS * QKV_COLS];
__device__ __half g_xh[(size_t)M_ROWS * DIM];
__device__ __half g_attnh[(size_t)M_ROWS * DIM];
__device__ __half g_wqkvh[(size_t)DIM * QKV_COLS];
__device__ __half g_wprojh[(size_t)DIM * DIM];
__device__ float  g_kvp[NCHUNK * 64 * HDIM * 72];     // fp32 partial kv_ext
__device__ __half g_kvh[64 * HDIM * 128];             // fp16 kv_ext; cols 72+ stay 0

// ---------------------------------------------------------------------------
// Main GEMM geometry: CTA 128x128, 8 warps (warp tile 32x64), KT=64, 3 stages
// ---------------------------------------------------------------------------
#define KT 64
#define NTILES (DIM / KT)
#define A_STAGE_BYTES (128 * 128)
#define B_STAGE_BYTES (64 * 256)
#define STAGE_BYTES (A_STAGE_BYTES + B_STAGE_BYTES)
#define GSTAGES 3
#define SMEM_BYTES (GSTAGES * STAGE_BYTES)   // 98304

__device__ __forceinline__ uint32_t smem_u32(const void* p) {
    uint32_t a;
    asm("{ .reg .u64 t; cvta.to.shared.u64 t, %1; cvt.u32.u64 %0, t; }"
        : "=r"(a) : "l"(p));
    return a;
}
__device__ __forceinline__ void cp16(uint32_t dst, const void* src) {
    asm volatile("cp.async.cg.shared.global [%0], [%1], 16;" :: "r"(dst), "l"(src));
}
__device__ __forceinline__ void ldsm4(uint32_t& r0, uint32_t& r1, uint32_t& r2,
                                      uint32_t& r3, uint32_t a) {
    asm volatile("ldmatrix.sync.aligned.m8n8.x4.shared.b16 {%0,%1,%2,%3}, [%4];"
                 : "=r"(r0), "=r"(r1), "=r"(r2), "=r"(r3) : "r"(a));
}
__device__ __forceinline__ void ldsm4t(uint32_t& r0, uint32_t& r1, uint32_t& r2,
                                       uint32_t& r3, uint32_t a) {
    asm volatile("ldmatrix.sync.aligned.m8n8.x4.trans.shared.b16 {%0,%1,%2,%3}, [%4];"
                 : "=r"(r0), "=r"(r1), "=r"(r2), "=r"(r3) : "r"(a));
}
__device__ __forceinline__ void mma16816(float* c, const uint32_t* a, const uint32_t* b) {
    asm volatile(
        "mma.sync.aligned.m16n8k16.row.col.f32.f16.f16.f32 "
        "{%0,%1,%2,%3}, {%4,%5,%6,%7}, {%8,%9}, {%0,%1,%2,%3};"
        : "+f"(c[0]), "+f"(c[1]), "+f"(c[2]), "+f"(c[3])
        : "r"(a[0]), "r"(a[1]), "r"(a[2]), "r"(a[3]), "r"(b[0]), "r"(b[1]));
}

// ---------------------------------------------------------------------------
// fp16 tensor GEMM with double-buffered fragments:
// C = Ah[M,1024] @ Bh[1024,N]; 8 warps, warp tile 32x64.
// MODE 1: elu+1 on cols<2048, half out.  MODE 2: +=bias, float out.
// ---------------------------------------------------------------------------
template <int MODE>
__global__ __launch_bounds__(256, 2) void gemm_h(
    const __half* __restrict__ Ah, const __half* __restrict__ Bh,
    void* __restrict__ Cv, int N, const float* __restrict__ bias)
{
    extern __shared__ char sm[];

    const int tid = threadIdx.x;
    const int bm = blockIdx.y * 128;
    const int bn = blockIdx.x * 128;
    const int lane = tid & 31, wid = tid >> 5;
    const int g = lane >> 2, tg = lane & 3;
    const int mw = (wid >> 1) * 32;
    const int nw = (wid & 1) * 64;
    const int l7 = lane & 7;
    const int grp = lane >> 3;

    float acc[2][8][4];
#pragma unroll
    for (int mi = 0; mi < 2; mi++)
#pragma unroll
        for (int ni = 0; ni < 8; ni++)
#pragma unroll
            for (int j = 0; j < 4; j++) acc[mi][ni][j] = 0.f;

    const uint32_t s0 = smem_u32(sm);

    auto load_tile = [&](int kt, int s) {
        const uint32_t sAl = s0 + s * STAGE_BYTES;
        const uint32_t sBl = sAl + A_STAGE_BYTES;
#pragma unroll
        for (int i = 0; i < 4; i++) {
            int id = tid + i * 256;
            int row = id >> 3, c = id & 7;
            cp16(sAl + row * 128 + ((c ^ (row & 7)) << 4),
                 Ah + (size_t)(bm + row) * DIM + kt * KT + c * 8);
        }
#pragma unroll
        for (int i = 0; i < 4; i++) {
            int id = tid + i * 256;
            int row = id >> 4, c = id & 15;
            cp16(sBl + row * 256 + ((c ^ (row & 7)) << 4),
                 Bh + (size_t)(kt * KT + row) * N + bn + c * 8);
        }
        asm volatile("cp.async.commit_group;" ::: "memory");
    };

    // hoisted fragment base addresses
    uint32_t aBase[2];
#pragma unroll
    for (int mi = 0; mi < 2; mi++) {
        int row = mw + mi * 16 + l7 + (grp & 1) * 8;
        aBase[mi] = row * 128 + (((grp >> 1) ^ (row & 7)) << 4);
    }
    uint32_t bBase[4];
#pragma unroll
    for (int nj = 0; nj < 4; nj++) {
        int brow = l7 + (grp & 1) * 8;
        int c = (nw >> 3) + nj * 2 + (grp >> 1);
        bBase[nj] = brow * 256 + ((c ^ l7) << 4);
    }

    load_tile(0, 0);
    load_tile(1, 1);

    int s = 0;
    for (int kt = 0; kt < NTILES; ++kt) {
        if (kt < NTILES - 1) {
            asm volatile("cp.async.wait_group 1;" ::: "memory");
        } else {
            asm volatile("cp.async.wait_group 0;" ::: "memory");
        }
        __syncthreads();

        const uint32_t sA = s0 + s * STAGE_BYTES;
        const uint32_t sB = sA + A_STAGE_BYTES;

        // ---- fragment double buffer: prologue (ks=0 -> buf 0) ----
        uint32_t af[2][2][4];
        uint32_t bf[2][8][2];
#pragma unroll
        for (int mi = 0; mi < 2; mi++)
            ldsm4(af[0][mi][0], af[0][mi][1], af[0][mi][2], af[0][mi][3],
                  sA + aBase[mi]);
#pragma unroll
        for (int nj = 0; nj < 4; nj++)
            ldsm4t(bf[0][2 * nj][0], bf[0][2 * nj][1],
                   bf[0][2 * nj + 1][0], bf[0][2 * nj + 1][1],
                   sB + bBase[nj]);

        // issue next-next tile loads after frag prologue
        if (kt + 2 < NTILES) {
            int s2 = s + 2; if (s2 >= GSTAGES) s2 -= GSTAGES;
            load_tile(kt + 2, s2);
        }

#pragma unroll
        for (int ks = 0; ks < 4; ks++) {
            const int cur = ks & 1, nxt = cur ^ 1;
            if (ks < 3) {
#pragma unroll
                for (int mi = 0; mi < 2; mi++)
                    ldsm4(af[nxt][mi][0], af[nxt][mi][1], af[nxt][mi][2], af[nxt][mi][3],
                          sA + (aBase[mi] ^ ((ks + 1) << 5)));
#pragma unroll
                for (int nj = 0; nj < 4; nj++)
                    ldsm4t(bf[nxt][2 * nj][0], bf[nxt][2 * nj][1],
                           bf[nxt][2 * nj + 1][0], bf[nxt][2 * nj + 1][1],
                           sB + bBase[nj] + (ks + 1) * 4096);
            }
#pragma unroll
            for (int mi = 0; mi < 2; mi++)
#pragma unroll
                for (int ni = 0; ni < 8; ni++)
                    mma16816(acc[mi][ni], af[cur][mi], bf[cur][ni]);
        }
        if (++s >= GSTAGES) s = 0;
    }

    // ---- epilogue ----
#pragma unroll
    for (int mi = 0; mi < 2; mi++) {
#pragma unroll
        for (int ni = 0; ni < 8; ni++) {
            const int row0 = bm + mw + mi * 16 + g;
            const int col = bn + nw + ni * 8 + 2 * tg;
            float v0 = acc[mi][ni][0], v1 = acc[mi][ni][1];
            float v2 = acc[mi][ni][2], v3 = acc[mi][ni][3];
            if (MODE == 1) {
                if (col < 2048) {                        // elu(x)+1 on q,k cols
                    v0 = (v0 > 0.f) ? (v0 + 1.f) : __expf(v0);
                    v1 = (v1 > 0.f) ? (v1 + 1.f) : __expf(v1);
                    v2 = (v2 > 0.f) ? (v2 + 1.f) : __expf(v2);
                    v3 = (v3 > 0.f) ? (v3 + 1.f) : __expf(v3);
                }
                __half* Ch = (__half*)Cv;
                *reinterpret_cast<__half2*>(&Ch[(size_t)row0 * N + col]) =
                    __floats2half2_rn(v0, v1);
                *reinterpret_cast<__half2*>(&Ch[(size_t)(row0 + 8) * N + col]) =
                    __floats2half2_rn(v2, v3);
            } else {
                float b0 = __ldg(&bias[col]), b1 = __ldg(&bias[col + 1]);
                v0 += b0; v1 += b1; v2 += b0; v3 += b1;
                float* Cf = (float*)Cv;
                *reinterpret_cast<float2*>(&Cf[(size_t)row0 * N + col]) = make_float2(v0, v1);
                *reinterpret_cast<float2*>(&Cf[(size_t)(row0 + 8) * N + col]) = make_float2(v2, v3);
            }
        }
    }
}

// ---------------------------------------------------------------------------
// Merged fp32 -> fp16 conversion (x, W_qkv, W_proj in one launch)
// ---------------------------------------------------------------------------
__global__ void convert_all_kernel(const float4* __restrict__ x, uint2* __restrict__ xh,
                                   const float4* __restrict__ wq, uint2* __restrict__ wqh,
                                   const float4* __restrict__ wp, uint2* __restrict__ wph)
{
    const int n1 = (int)((size_t)M_ROWS * DIM / 4);
    const int n2 = (int)((size_t)DIM * QKV_COLS / 4);
    const int n3 = (int)((size_t)DIM * DIM / 4);
    const int stride = gridDim.x * blockDim.x;
    int i0 = blockIdx.x * blockDim.x + threadIdx.x;
    for (int i = i0; i < n1; i += stride) {
        float4 v = x[i];
        __half2 a = __floats2half2_rn(v.x, v.y), b = __floats2half2_rn(v.z, v.w);
        uint2 o; o.x = *(uint32_t*)&a; o.y = *(uint32_t*)&b; xh[i] = o;
    }
    for (int i = i0; i < n2; i += stride) {
        float4 v = wq[i];
        __half2 a = __floats2half2_rn(v.x, v.y), b = __floats2half2_rn(v.z, v.w);
        uint2 o; o.x = *(uint32_t*)&a; o.y = *(uint32_t*)&b; wqh[i] = o;
    }
    for (int i = i0; i < n3; i += stride) {
        float4 v = wp[i];
        __half2 a = __floats2half2_rn(v.x, v.y), b = __floats2half2_rn(v.z, v.w);
        uint2 o; o.x = *(uint32_t*)&a; o.y = *(uint32_t*)&b; wph[i] = o;
    }
}

// ---------------------------------------------------------------------------
// K2a (tensor): per (bh, chunk): kv_ext[64 d][72] += k[n,d]*vext[n,e] over
// 512 seq rows; vext col 64 = 1.0 (ksum), cols 65-71 = 0.
// ---------------------------------------------------------------------------
#define K2_K_STAGE_B (64 * 128)
#define K2_V_STAGE_B (64 * 256)
#define K2_STAGE_B (K2_K_STAGE_B + K2_V_STAGE_B)
#define K2_SMEM (3 * K2_STAGE_B)
#define K2_NT (CHUNK_ROWS / 64)      // 8 k-tiles

__global__ __launch_bounds__(128) void kv_partial_tc()
{
    extern __shared__ char sm2[];
    const int bh = blockIdx.x;
    const int chunk = blockIdx.y;
    const int b = bh >> 4, h = bh & 15;

    const int tid = threadIdx.x;
    const int lane = tid & 31, wid = tid >> 5;
    const int g = lane >> 2, tg = lane & 3;
    const int l7 = lane & 7;
    const int grp = lane >> 3;
    const uint32_t s0 = smem_u32(sm2);

    // init ones-column chunk (chunk 8 of v tile) for all 3 stages
    for (int idx = tid; idx < 3 * 64; idx += 128) {
        int st = idx >> 6, r = idx & 63;
        uint32_t a = s0 + st * K2_STAGE_B + K2_K_STAGE_B + r * 256 + ((8 ^ (r & 7)) << 4);
        asm volatile("st.shared.v4.b32 [%0], {%1, %2, %3, %4};"
                     :: "r"(a), "r"(0x00003C00u), "r"(0u), "r"(0u), "r"(0u));
    }

    float acc[9][4];
#pragma unroll
    for (int nj = 0; nj < 9; nj++)
#pragma unroll
        for (int j = 0; j < 4; j++) acc[nj][j] = 0.f;

    const __half* baseh = g_qkvh + (size_t)b * SEQ * QKV_COLS;
    const int k_col = DIM + h * HDIM;
    const int v_col = 2 * DIM + h * HDIM;
    const int nbase = chunk * CHUNK_ROWS;

    auto load_tile = [&](int kt, int st) {
        const uint32_t sK = s0 + st * K2_STAGE_B;
        const uint32_t sV = sK + K2_K_STAGE_B;
        const int n0 = nbase + kt * 64;
#pragma unroll
        for (int i = 0; i < 4; i++) {
            int id = tid + i * 128;
            int row = id >> 3, c = id & 7;
            cp16(sK + row * 128 + ((c ^ (row & 7)) << 4),
                 baseh + (size_t)(n0 + row) * QKV_COLS + k_col + c * 8);
        }
#pragma unroll
        for (int i = 0; i < 4; i++) {
            int id = tid + i * 128;
            int row = id >> 3, c = id & 7;
            cp16(sV + row * 256 + ((c ^ (row & 7)) << 4),
                 baseh + (size_t)(n0 + row) * QKV_COLS + v_col + c * 8);
        }
        asm volatile("cp.async.commit_group;" ::: "memory");
    };

    const uint32_t aOff = (l7 + (grp >> 1) * 8) * 128 +
                          (((wid * 2 + (grp & 1)) ^ l7) << 4);
    uint32_t bOff[5];
#pragma unroll
    for (int p = 0; p < 5; p++)
        bOff[p] = (l7 + (grp & 1) * 8) * 256 + (((p * 2 + (grp >> 1)) ^ l7) << 4);

    load_tile(0, 0);
    load_tile(1, 1);

    int st = 0;
    for (int kt = 0; kt < K2_NT; ++kt) {
        if (kt < K2_NT - 1) {
            asm volatile("cp.async.wait_group 1;" ::: "memory");
        } else {
            asm volatile("cp.async.wait_group 0;" ::: "memory");
        }
        __syncthreads();
        if (kt + 2 < K2_NT) {
            int s2 = st + 2; if (s2 >= 3) s2 -= 3;
            load_tile(kt + 2, s2);
        }

        const uint32_t sK = s0 + st * K2_STAGE_B;
        const uint32_t sV = sK + K2_K_STAGE_B;

#pragma unroll
        for (int ks = 0; ks < 4; ks++) {
            uint32_t af[4];
            ldsm4t(af[0], af[1], af[2], af[3], sK + aOff + ks * 2048);
            uint32_t bf[10][2];
#pragma unroll
            for (int p = 0; p < 5; p++)
                ldsm4t(bf[2 * p][0], bf[2 * p][1], bf[2 * p + 1][0], bf[2 * p + 1][1],
                       sV + bOff[p] + ks * 4096);
#pragma unroll
            for (int nj = 0; nj < 9; nj++)
                mma16816(acc[nj], af, bf[nj]);
        }
        if (++st >= 3) st = 0;
    }

    float* outp = g_kvp + ((size_t)chunk * 64 + bh) * (HDIM * 72);
#pragma unroll
    for (int nj = 0; nj < 9; nj++) {
        int d0 = wid * 16 + g;
        int e = nj * 8 + 2 * tg;
        *reinterpret_cast<float2*>(&outp[d0 * 72 + e]) = make_float2(acc[nj][0], acc[nj][1]);
        *reinterpret_cast<float2*>(&outp[(d0 + 8) * 72 + e]) = make_float2(acc[nj][2], acc[nj][3]);
    }
}

// K2b: deterministic reduce over chunks -> fp16 kv_ext cols 0-71 (float2 path)
__global__ __launch_bounds__(128) void kv_reduce_kernel()
{
    const int bh = blockIdx.x;
    const int d0 = blockIdx.y * 8;
    const int tid = threadIdx.x;
    for (int idx = tid; idx < 8 * 36; idx += 128) {
        int d = d0 + idx / 36, e2 = (idx % 36) * 2;
        float sx = 0.f, sy = 0.f;
#pragma unroll
        for (int c = 0; c < NCHUNK; c++) {
            float2 v = *reinterpret_cast<const float2*>(
                &g_kvp[((size_t)c * 64 + bh) * (HDIM * 72) + d * 72 + e2]);
            sx += v.x; sy += v.y;
        }
        *reinterpret_cast<__half2*>(&g_kvh[(size_t)bh * HDIM * 128 + d * 128 + e2]) =
            __floats2half2_rn(sx, sy);
    }
}

// ---------------------------------------------------------------------------
// K3 (tensor): O = Q[64x64] @ KV_ext[64x72]; col 64 -> z; store fp16 attn
// ---------------------------------------------------------------------------
__global__ __launch_bounds__(128) void attn_out_tc()
{
    __shared__ __align__(16) char qbuf[64 * 128];
    __shared__ __align__(16) char kvbuf[64 * 256];

    const int bh = blockIdx.y;
    const int b = bh >> 4, h = bh & 15;
    const int n0 = blockIdx.x * 64;

    const int tid = threadIdx.x;
    const int lane = tid & 31, wid = tid >> 5;
    const int g = lane >> 2, tg = lane & 3;
    const int l7 = lane & 7;
    const int grp = lane >> 3;

    const uint32_t sQ = smem_u32(qbuf);
    const uint32_t sKV = smem_u32(kvbuf);

    const __half* qsrc = g_qkvh + (size_t)(b * SEQ + n0) * QKV_COLS + h * HDIM;
#pragma unroll
    for (int i = 0; i < 4; i++) {
        int id = tid + i * 128;
        int row = id >> 3, c = id & 7;
        cp16(sQ + row * 128 + ((c ^ (row & 7)) << 4),
             qsrc + (size_t)row * QKV_COLS + c * 8);
    }
    // kv tile: only chunks 0-9 per row are read by the ldmatrix pattern
    const __half* kvsrc = g_kvh + (size_t)bh * HDIM * 128;
#pragma unroll
    for (int i = 0; i < 5; i++) {
        int id = tid + i * 128;
        int row = id / 10, c = id % 10;
        cp16(sKV + row * 256 + ((c ^ (row & 7)) << 4), kvsrc + row * 128 + c * 8);
    }
    asm volatile("cp.async.commit_group;" ::: "memory");
    asm volatile("cp.async.wait_group 0;" ::: "memory");
    __syncthreads();

    float acc[9][4];
#pragma unroll
    for (int nj = 0; nj < 9; nj++)
#pragma unroll
        for (int j = 0; j < 4; j++) acc[nj][j] = 0.f;

    const int arow = wid * 16 + l7 + (grp & 1) * 8;
    const uint32_t aBase = arow * 128 + (((grp >> 1) ^ (arow & 7)) << 4);
    uint32_t bOff[5];
#pragma unroll
    for (int p = 0; p < 5; p++)
        bOff[p] = (l7 + (grp & 1) * 8) * 256 + (((p * 2 + (grp >> 1)) ^ l7) << 4);

#pragma unroll
    for (int ks = 0; ks < 4; ks++) {
        uint32_t af[4];
        ldsm4(af[0], af[1], af[2], af[3], sQ + (aBase ^ (ks << 5)));
        uint32_t bf[10][2];
#pragma unroll
        for (int p = 0; p < 5; p++)
            ldsm4t(bf[2 * p][0], bf[2 * p][1], bf[2 * p + 1][0], bf[2 * p + 1][1],
                   sKV + bOff[p] + ks * 4096);
#pragma unroll
        for (int nj = 0; nj < 9; nj++)
            mma16816(acc[nj], af, bf[nj]);
    }

    float dlo = __shfl_sync(0xffffffffu, acc[8][0], lane & 28);
    float dhi = __shfl_sync(0xffffffffu, acc[8][2], lane & 28);
    float zlo = 1.f / (dlo + 1e-6f);
    float zhi = 1.f / (dhi + 1e-6f);

    __half* outp = g_attnh + (size_t)(b * SEQ + n0) * DIM + h * HDIM;
#pragma unroll
    for (int nj = 0; nj < 8; nj++) {
        int r = wid * 16 + g;
        int e = nj * 8 + 2 * tg;
        *reinterpret_cast<__half2*>(&outp[(size_t)r * DIM + e]) =
            __floats2half2_rn(acc[nj][0] * zlo, acc[nj][1] * zlo);
        *reinterpret_cast<__half2*>(&outp[(size_t)(r + 8) * DIM + e]) =
            __floats2half2_rn(acc[nj][2] * zhi, acc[nj][3] * zhi);
    }
}

// ---------------------------------------------------------------------------
extern "C" void kernel_launch(void* const* d_in, const int* in_sizes, int n_in,
                              void* d_out, int out_size)
{
    const float* x      = (const float*)d_in[0];
    const float* W_qkv  = (const float*)d_in[1];
    const float* W_proj = (const float*)d_in[2];
    const float* b_proj = (const float*)d_in[3];
    float* out = (float*)d_out;

    __half *qkvh_p, *xh_p, *attnh_p, *wqkvh_p, *wprojh_p;
    cudaGetSymbolAddress((void**)&qkvh_p, g_qkvh);
    cudaGetSymbolAddress((void**)&xh_p, g_xh);
    cudaGetSymbolAddress((void**)&attnh_p, g_attnh);
    cudaGetSymbolAddress((void**)&wqkvh_p, g_wqkvh);
    cudaGetSymbolAddress((void**)&wprojh_p, g_wprojh);

    cudaFuncSetAttribute(gemm_h<1>, cudaFuncAttributeMaxDynamicSharedMemorySize, SMEM_BYTES);
    cudaFuncSetAttribute(gemm_h<2>, cudaFuncAttributeMaxDynamicSharedMemorySize, SMEM_BYTES);
    cudaFuncSetAttribute(kv_partial_tc, cudaFuncAttributeMaxDynamicSharedMemorySize, K2_SMEM);

    convert_all_kernel<<<2048, 256>>>((const float4*)x, (uint2*)xh_p,
                                      (const float4*)W_qkv, (uint2*)wqkvh_p,
                                      (const float4*)W_proj, (uint2*)wprojh_p);

    // K1: qkv = x @ W_qkv (fp16 out), elu+1 fused on q/k columns
    gemm_h<1><<<dim3(QKV_COLS / 128, M_ROWS / 128), 256, SMEM_BYTES>>>(
        xh_p, wqkvh_p, qkvh_p, QKV_COLS, nullptr);

    // K2: kv_ext partials (tensor cores, ones-column ksum) + reduce
    kv_partial_tc<<<dim3(64, NCHUNK), 128, K2_SMEM>>>();
    kv_reduce_kernel<<<dim3(64, 8), 128>>>();

    // K3: normalized readout (tensor cores, fused z via column 64)
    attn_out_tc<<<dim3(SEQ / 64, 64), 128>>>();

    // K4: out = attn @ W_proj + b_proj (fp32 out)
    gemm_h<2><<<dim3(DIM / 128, M_ROWS / 128), 256, SMEM_BYTES>>>(
        attnh_p, wprojh_p, out, DIM, b_proj);
}

// round 12
// speedup vs baseline: 1.0716x; 1.0716x over previous
#include <cuda_runtime.h>
#include <cuda_fp16.h>
#include <math.h>
#include <stdint.h>

// ---------------------------------------------------------------------------
// Problem constants
// ---------------------------------------------------------------------------
#define BATCH 4
#define SEQ 4096
#define DIM 1024
#define NHEAD 16
#define HDIM 64
#define M_ROWS (BATCH * SEQ)      // 16384
#define QKV_COLS (3 * DIM)        // 3072
#define NCHUNK 8
#define CHUNK_ROWS (SEQ / NCHUNK) // 512

// Scratch (device globals; allocation-free contract)
__device__ __half g_qkvh[(size_t)M_ROWS * QKV_COLS];
__device__ __half g_xh[(size_t)M_ROWS * DIM];
__device__ __half g_attnh[(size_t)M_ROWS * DIM];
__device__ __half g_wqkvh[(size_t)DIM * QKV_COLS];
__device__ __half g_wprojh[(size_t)DIM * DIM];
__device__ float  g_kvp[NCHUNK * 64 * HDIM * 72];     // fp32 partial kv_ext
__device__ __half g_kvh[64 * HDIM * 128];             // fp16 kv_ext; cols 72+ stay 0

// ---------------------------------------------------------------------------
// Main GEMM geometry (R10 config): CTA 128x128, 8 warps (warp tile 32x64),
// KT=64, 3-stage cp.async, one __syncthreads per k-tile.
// ---------------------------------------------------------------------------
#define KT 64
#define NTILES (DIM / KT)
#define A_STAGE_BYTES (128 * 128)
#define B_STAGE_BYTES (64 * 256)
#define STAGE_BYTES (A_STAGE_BYTES + B_STAGE_BYTES)
#define GSTAGES 3
#define SMEM_BYTES (GSTAGES * STAGE_BYTES)   // 98304

__device__ __forceinline__ uint32_t smem_u32(const void* p) {
    uint32_t a;
    asm("{ .reg .u64 t; cvta.to.shared.u64 t, %1; cvt.u32.u64 %0, t; }"
        : "=r"(a) : "l"(p));
    return a;
}
__device__ __forceinline__ void cp16(uint32_t dst, const void* src) {
    asm volatile("cp.async.cg.shared.global [%0], [%1], 16;" :: "r"(dst), "l"(src));
}
__device__ __forceinline__ void ldsm4(uint32_t& r0, uint32_t& r1, uint32_t& r2,
                                      uint32_t& r3, uint32_t a) {
    asm volatile("ldmatrix.sync.aligned.m8n8.x4.shared.b16 {%0,%1,%2,%3}, [%4];"
                 : "=r"(r0), "=r"(r1), "=r"(r2), "=r"(r3) : "r"(a));
}
__device__ __forceinline__ void ldsm4t(uint32_t& r0, uint32_t& r1, uint32_t& r2,
                                       uint32_t& r3, uint32_t a) {
    asm volatile("ldmatrix.sync.aligned.m8n8.x4.trans.shared.b16 {%0,%1,%2,%3}, [%4];"
                 : "=r"(r0), "=r"(r1), "=r"(r2), "=r"(r3) : "r"(a));
}
__device__ __forceinline__ void mma16816(float* c, const uint32_t* a, const uint32_t* b) {
    asm volatile(
        "mma.sync.aligned.m16n8k16.row.col.f32.f16.f16.f32 "
        "{%0,%1,%2,%3}, {%4,%5,%6,%7}, {%8,%9}, {%0,%1,%2,%3};"
        : "+f"(c[0]), "+f"(c[1]), "+f"(c[2]), "+f"(c[3])
        : "r"(a[0]), "r"(a[1]), "r"(a[2]), "r"(a[3]), "r"(b[0]), "r"(b[1]));
}

// ---------------------------------------------------------------------------
// fp16 tensor GEMM (R10 config): C = Ah[M,1024] @ Bh[1024,N].
// MODE 1: elu+1 on cols<2048, half out.  MODE 2: +=bias, float out.
// ---------------------------------------------------------------------------
template <int MODE>
__global__ __launch_bounds__(256, 2) void gemm_h(
    const __half* __restrict__ Ah, const __half* __restrict__ Bh,
    void* __restrict__ Cv, int N, const float* __restrict__ bias)
{
    extern __shared__ char sm[];

    const int tid = threadIdx.x;
    const int bm = blockIdx.y * 128;
    const int bn = blockIdx.x * 128;
    const int lane = tid & 31, wid = tid >> 5;
    const int g = lane >> 2, tg = lane & 3;
    const int mw = (wid >> 1) * 32;
    const int nw = (wid & 1) * 64;
    const int l7 = lane & 7;
    const int grp = lane >> 3;

    float acc[2][8][4];
#pragma unroll
    for (int mi = 0; mi < 2; mi++)
#pragma unroll
        for (int ni = 0; ni < 8; ni++)
#pragma unroll
            for (int j = 0; j < 4; j++) acc[mi][ni][j] = 0.f;

    const uint32_t s0 = smem_u32(sm);

    uint32_t ldA_s[4], ldB_s[4];
#pragma unroll
    for (int i = 0; i < 4; i++) {
        int id = tid + i * 256;
        int row = id >> 3, c = id & 7;
        ldA_s[i] = row * 128 + ((c ^ (row & 7)) << 4);
        int rowb = id >> 4, cb = id & 15;
        ldB_s[i] = rowb * 256 + ((cb ^ (rowb & 7)) << 4);
    }

    auto load_tile = [&](int kt, int s) {
        const uint32_t sA = s0 + s * STAGE_BYTES;
        const uint32_t sB = sA + A_STAGE_BYTES;
#pragma unroll
        for (int i = 0; i < 4; i++) {
            int id = tid + i * 256;
            int row = id >> 3, c = id & 7;
            cp16(sA + ldA_s[i], Ah + (size_t)(bm + row) * DIM + kt * KT + c * 8);
        }
#pragma unroll
        for (int i = 0; i < 4; i++) {
            int id = tid + i * 256;
            int row = id >> 4, c = id & 15;
            cp16(sB + ldB_s[i], Bh + (size_t)(kt * KT + row) * N + bn + c * 8);
        }
        asm volatile("cp.async.commit_group;" ::: "memory");
    };

    uint32_t aBase[2];
#pragma unroll
    for (int mi = 0; mi < 2; mi++) {
        int row = mw + mi * 16 + l7 + (grp & 1) * 8;
        aBase[mi] = row * 128 + (((grp >> 1) ^ (row & 7)) << 4);
    }
    uint32_t bBase[4];
#pragma unroll
    for (int nj = 0; nj < 4; nj++) {
        int brow = l7 + (grp & 1) * 8;
        int c = (nw >> 3) + nj * 2 + (grp >> 1);
        bBase[nj] = brow * 256 + ((c ^ l7) << 4);
    }

    load_tile(0, 0);
    load_tile(1, 1);

    int s = 0;
    for (int kt = 0; kt < NTILES; ++kt) {
        if (kt < NTILES - 1) {
            asm volatile("cp.async.wait_group 1;" ::: "memory");
        } else {
            asm volatile("cp.async.wait_group 0;" ::: "memory");
        }
        __syncthreads();
        if (kt + 2 < NTILES) {
            int s2 = s + 2; if (s2 >= GSTAGES) s2 -= GSTAGES;
            load_tile(kt + 2, s2);
        }

        const uint32_t sA = s0 + s * STAGE_BYTES;
        const uint32_t sB = sA + A_STAGE_BYTES;

#pragma unroll
        for (int ks = 0; ks < 4; ks++) {
            uint32_t af[2][4];
#pragma unroll
            for (int mi = 0; mi < 2; mi++)
                ldsm4(af[mi][0], af[mi][1], af[mi][2], af[mi][3],
                      sA + (aBase[mi] ^ (ks << 5)));
            uint32_t bf[8][2];
#pragma unroll
            for (int nj = 0; nj < 4; nj++)
                ldsm4t(bf[2 * nj][0], bf[2 * nj][1], bf[2 * nj + 1][0], bf[2 * nj + 1][1],
                       sB + bBase[nj] + ks * 4096);
#pragma unroll
            for (int mi = 0; mi < 2; mi++)
#pragma unroll
                for (int ni = 0; ni < 8; ni++)
                    mma16816(acc[mi][ni], af[mi], bf[ni]);
        }
        if (++s >= GSTAGES) s = 0;
    }

    // ---- epilogue ----
    const bool do_elu = (MODE == 1) && (bn < 2048);   // CTA-uniform predicate
#pragma unroll
    for (int mi = 0; mi < 2; mi++) {
#pragma unroll
        for (int ni = 0; ni < 8; ni++) {
            const int row0 = bm + mw + mi * 16 + g;
            const int col = bn + nw + ni * 8 + 2 * tg;
            float v0 = acc[mi][ni][0], v1 = acc[mi][ni][1];
            float v2 = acc[mi][ni][2], v3 = acc[mi][ni][3];
            if (MODE == 1) {
                if (do_elu) {                         // elu(x)+1 on q,k cols
                    v0 = (v0 > 0.f) ? (v0 + 1.f) : __expf(v0);
                    v1 = (v1 > 0.f) ? (v1 + 1.f) : __expf(v1);
                    v2 = (v2 > 0.f) ? (v2 + 1.f) : __expf(v2);
                    v3 = (v3 > 0.f) ? (v3 + 1.f) : __expf(v3);
                }
                __half* Ch = (__half*)Cv;
                *reinterpret_cast<__half2*>(&Ch[(size_t)row0 * N + col]) =
                    __floats2half2_rn(v0, v1);
                *reinterpret_cast<__half2*>(&Ch[(size_t)(row0 + 8) * N + col]) =
                    __floats2half2_rn(v2, v3);
            } else {
                float b0 = __ldg(&bias[col]), b1 = __ldg(&bias[col + 1]);
                v0 += b0; v1 += b1; v2 += b0; v3 += b1;
                float* Cf = (float*)Cv;
                *reinterpret_cast<float2*>(&Cf[(size_t)row0 * N + col]) = make_float2(v0, v1);
                *reinterpret_cast<float2*>(&Cf[(size_t)(row0 + 8) * N + col]) = make_float2(v2, v3);
            }
        }
    }
}

// ---------------------------------------------------------------------------
// Merged fp32 -> fp16 conversion (x, W_qkv, W_proj in one launch)
// ---------------------------------------------------------------------------
__global__ void convert_all_kernel(const float4* __restrict__ x, uint2* __restrict__ xh,
                                   const float4* __restrict__ wq, uint2* __restrict__ wqh,
                                   const float4* __restrict__ wp, uint2* __restrict__ wph)
{
    const int n1 = (int)((size_t)M_ROWS * DIM / 4);
    const int n2 = (int)((size_t)DIM * QKV_COLS / 4);
    const int n3 = (int)((size_t)DIM * DIM / 4);
    const int stride = gridDim.x * blockDim.x;
    int i0 = blockIdx.x * blockDim.x + threadIdx.x;
    for (int i = i0; i < n1; i += stride) {
        float4 v = x[i];
        __half2 a = __floats2half2_rn(v.x, v.y), b = __floats2half2_rn(v.z, v.w);
        uint2 o; o.x = *(uint32_t*)&a; o.y = *(uint32_t*)&b; xh[i] = o;
    }
    for (int i = i0; i < n2; i += stride) {
        float4 v = wq[i];
        __half2 a = __floats2half2_rn(v.x, v.y), b = __floats2half2_rn(v.z, v.w);
        uint2 o; o.x = *(uint32_t*)&a; o.y = *(uint32_t*)&b; wqh[i] = o;
    }
    for (int i = i0; i < n3; i += stride) {
        float4 v = wp[i];
        __half2 a = __floats2half2_rn(v.x, v.y), b = __floats2half2_rn(v.z, v.w);
        uint2 o; o.x = *(uint32_t*)&a; o.y = *(uint32_t*)&b; wph[i] = o;
    }
}

// ---------------------------------------------------------------------------
// K2a (tensor): per (bh, chunk): kv_ext[64 d][72] += k[n,d]*vext[n,e] over
// 512 seq rows; vext col 64 = 1.0 (ksum), cols 65-71 = 0.
// ---------------------------------------------------------------------------
#define K2_K_STAGE_B (64 * 128)
#define K2_V_STAGE_B (64 * 256)
#define K2_STAGE_B (K2_K_STAGE_B + K2_V_STAGE_B)
#define K2_SMEM (3 * K2_STAGE_B)
#define K2_NT (CHUNK_ROWS / 64)      // 8 k-tiles

__global__ __launch_bounds__(128) void kv_partial_tc()
{
    extern __shared__ char sm2[];
    const int bh = blockIdx.x;
    const int chunk = blockIdx.y;
    const int b = bh >> 4, h = bh & 15;

    const int tid = threadIdx.x;
    const int lane = tid & 31, wid = tid >> 5;
    const int g = lane >> 2, tg = lane & 3;
    const int l7 = lane & 7;
    const int grp = lane >> 3;
    const uint32_t s0 = smem_u32(sm2);

    // init ones-column chunk (chunk 8 of v tile) for all 3 stages
    for (int idx = tid; idx < 3 * 64; idx += 128) {
        int st = idx >> 6, r = idx & 63;
        uint32_t a = s0 + st * K2_STAGE_B + K2_K_STAGE_B + r * 256 + ((8 ^ (r & 7)) << 4);
        asm volatile("st.shared.v4.b32 [%0], {%1, %2, %3, %4};"
                     :: "r"(a), "r"(0x00003C00u), "r"(0u), "r"(0u), "r"(0u));
    }

    float acc[9][4];
#pragma unroll
    for (int nj = 0; nj < 9; nj++)
#pragma unroll
        for (int j = 0; j < 4; j++) acc[nj][j] = 0.f;

    const __half* baseh = g_qkvh + (size_t)b * SEQ * QKV_COLS;
    const int k_col = DIM + h * HDIM;
    const int v_col = 2 * DIM + h * HDIM;
    const int nbase = chunk * CHUNK_ROWS;

    auto load_tile = [&](int kt, int st) {
        const uint32_t sK = s0 + st * K2_STAGE_B;
        const uint32_t sV = sK + K2_K_STAGE_B;
        const int n0 = nbase + kt * 64;
#pragma unroll
        for (int i = 0; i < 4; i++) {
            int id = tid + i * 128;
            int row = id >> 3, c = id & 7;
            cp16(sK + row * 128 + ((c ^ (row & 7)) << 4),
                 baseh + (size_t)(n0 + row) * QKV_COLS + k_col + c * 8);
        }
#pragma unroll
        for (int i = 0; i < 4; i++) {
            int id = tid + i * 128;
            int row = id >> 3, c = id & 7;
            cp16(sV + row * 256 + ((c ^ (row & 7)) << 4),
                 baseh + (size_t)(n0 + row) * QKV_COLS + v_col + c * 8);
        }
        asm volatile("cp.async.commit_group;" ::: "memory");
    };

    const uint32_t aOff = (l7 + (grp >> 1) * 8) * 128 +
                          (((wid * 2 + (grp & 1)) ^ l7) << 4);
    uint32_t bOff[5];
#pragma unroll
    for (int p = 0; p < 5; p++)
        bOff[p] = (l7 + (grp & 1) * 8) * 256 + (((p * 2 + (grp >> 1)) ^ l7) << 4);

    load_tile(0, 0);
    load_tile(1, 1);

    int st = 0;
    for (int kt = 0; kt < K2_NT; ++kt) {
        if (kt < K2_NT - 1) {
            asm volatile("cp.async.wait_group 1;" ::: "memory");
        } else {
            asm volatile("cp.async.wait_group 0;" ::: "memory");
        }
        __syncthreads();
        if (kt + 2 < K2_NT) {
            int s2 = st + 2; if (s2 >= 3) s2 -= 3;
            load_tile(kt + 2, s2);
        }

        const uint32_t sK = s0 + st * K2_STAGE_B;
        const uint32_t sV = sK + K2_K_STAGE_B;

#pragma unroll
        for (int ks = 0; ks < 4; ks++) {
            uint32_t af[4];
            ldsm4t(af[0], af[1], af[2], af[3], sK + aOff + ks * 2048);
            uint32_t bf[10][2];
#pragma unroll
            for (int p = 0; p < 5; p++)
                ldsm4t(bf[2 * p][0], bf[2 * p][1], bf[2 * p + 1][0], bf[2 * p + 1][1],
                       sV + bOff[p] + ks * 4096);
#pragma unroll
            for (int nj = 0; nj < 9; nj++)
                mma16816(acc[nj], af, bf[nj]);
        }
        if (++st >= 3) st = 0;
    }

    float* outp = g_kvp + ((size_t)chunk * 64 + bh) * (HDIM * 72);
#pragma unroll
    for (int nj = 0; nj < 9; nj++) {
        int d0 = wid * 16 + g;
        int e = nj * 8 + 2 * tg;
        *reinterpret_cast<float2*>(&outp[d0 * 72 + e]) = make_float2(acc[nj][0], acc[nj][1]);
        *reinterpret_cast<float2*>(&outp[(d0 + 8) * 72 + e]) = make_float2(acc[nj][2], acc[nj][3]);
    }
}

// K2b: deterministic reduce over chunks -> fp16 kv_ext cols 0-71 (float2 path)
__global__ __launch_bounds__(128) void kv_reduce_kernel()
{
    const int bh = blockIdx.x;
    const int d0 = blockIdx.y * 8;
    const int tid = threadIdx.x;
    for (int idx = tid; idx < 8 * 36; idx += 128) {
        int d = d0 + idx / 36, e2 = (idx % 36) * 2;
        float sx = 0.f, sy = 0.f;
#pragma unroll
        for (int c = 0; c < NCHUNK; c++) {
            float2 v = *reinterpret_cast<const float2*>(
                &g_kvp[((size_t)c * 64 + bh) * (HDIM * 72) + d * 72 + e2]);
            sx += v.x; sy += v.y;
        }
        *reinterpret_cast<__half2*>(&g_kvh[(size_t)bh * HDIM * 128 + d * 128 + e2]) =
            __floats2half2_rn(sx, sy);
    }
}

// ---------------------------------------------------------------------------
// K3 (tensor): O = Q[64x64] @ KV_ext[64x72]; col 64 -> z; store fp16 attn
// ---------------------------------------------------------------------------
__global__ __launch_bounds__(128) void attn_out_tc()
{
    __shared__ __align__(16) char qbuf[64 * 128];
    __shared__ __align__(16) char kvbuf[64 * 256];

    const int bh = blockIdx.y;
    const int b = bh >> 4, h = bh & 15;
    const int n0 = blockIdx.x * 64;

    const int tid = threadIdx.x;
    const int lane = tid & 31, wid = tid >> 5;
    const int g = lane >> 2, tg = lane & 3;
    const int l7 = lane & 7;
    const int grp = lane >> 3;

    const uint32_t sQ = smem_u32(qbuf);
    const uint32_t sKV = smem_u32(kvbuf);

    const __half* qsrc = g_qkvh + (size_t)(b * SEQ + n0) * QKV_COLS + h * HDIM;
#pragma unroll
    for (int i = 0; i < 4; i++) {
        int id = tid + i * 128;
        int row = id >> 3, c = id & 7;
        cp16(sQ + row * 128 + ((c ^ (row & 7)) << 4),
             qsrc + (size_t)row * QKV_COLS + c * 8);
    }
    // kv tile: only chunks 0-9 per row are read by the ldmatrix pattern
    const __half* kvsrc = g_kvh + (size_t)bh * HDIM * 128;
#pragma unroll
    for (int i = 0; i < 5; i++) {
        int id = tid + i * 128;
        int row = id / 10, c = id % 10;
        cp16(sKV + row * 256 + ((c ^ (row & 7)) << 4), kvsrc + row * 128 + c * 8);
    }
    asm volatile("cp.async.commit_group;" ::: "memory");
    asm volatile("cp.async.wait_group 0;" ::: "memory");
    __syncthreads();

    float acc[9][4];
#pragma unroll
    for (int nj = 0; nj < 9; nj++)
#pragma unroll
        for (int j = 0; j < 4; j++) acc[nj][j] = 0.f;

    const int arow = wid * 16 + l7 + (grp & 1) * 8;
    const uint32_t aBase = arow * 128 + (((grp >> 1) ^ (arow & 7)) << 4);
    uint32_t bOff[5];
#pragma unroll
    for (int p = 0; p < 5; p++)
        bOff[p] = (l7 + (grp & 1) * 8) * 256 + (((p * 2 + (grp >> 1)) ^ l7) << 4);

#pragma unroll
    for (int ks = 0; ks < 4; ks++) {
        uint32_t af[4];
        ldsm4(af[0], af[1], af[2], af[3], sQ + (aBase ^ (ks << 5)));
        uint32_t bf[10][2];
#pragma unroll
        for (int p = 0; p < 5; p++)
            ldsm4t(bf[2 * p][0], bf[2 * p][1], bf[2 * p + 1][0], bf[2 * p + 1][1],
                   sKV + bOff[p] + ks * 4096);
#pragma unroll
        for (int nj = 0; nj < 9; nj++)
            mma16816(acc[nj], af, bf[nj]);
    }

    float dlo = __shfl_sync(0xffffffffu, acc[8][0], lane & 28);
    float dhi = __shfl_sync(0xffffffffu, acc[8][2], lane & 28);
    float zlo = 1.f / (dlo + 1e-6f);
    float zhi = 1.f / (dhi + 1e-6f);

    __half* outp = g_attnh + (size_t)(b * SEQ + n0) * DIM + h * HDIM;
#pragma unroll
    for (int nj = 0; nj < 8; nj++) {
        int r = wid * 16 + g;
        int e = nj * 8 + 2 * tg;
        *reinterpret_cast<__half2*>(&outp[(size_t)r * DIM + e]) =
            __floats2half2_rn(acc[nj][0] * zlo, acc[nj][1] * zlo);
        *reinterpret_cast<__half2*>(&outp[(size_t)(r + 8) * DIM + e]) =
            __floats2half2_rn(acc[nj][2] * zhi, acc[nj][3] * zhi);
    }
}

// ---------------------------------------------------------------------------
extern "C" void kernel_launch(void* const* d_in, const int* in_sizes, int n_in,
                              void* d_out, int out_size)
{
    const float* x      = (const float*)d_in[0];
    const float* W_qkv  = (const float*)d_in[1];
    const float* W_proj = (const float*)d_in[2];
    const float* b_proj = (const float*)d_in[3];
    float* out = (float*)d_out;

    __half *qkvh_p, *xh_p, *attnh_p, *wqkvh_p, *wprojh_p;
    cudaGetSymbolAddress((void**)&qkvh_p, g_qkvh);
    cudaGetSymbolAddress((void**)&xh_p, g_xh);
    cudaGetSymbolAddress((void**)&attnh_p, g_attnh);
    cudaGetSymbolAddress((void**)&wqkvh_p, g_wqkvh);
    cudaGetSymbolAddress((void**)&wprojh_p, g_wprojh);

    cudaFuncSetAttribute(gemm_h<1>, cudaFuncAttributeMaxDynamicSharedMemorySize, SMEM_BYTES);
    cudaFuncSetAttribute(gemm_h<2>, cudaFuncAttributeMaxDynamicSharedMemorySize, SMEM_BYTES);
    cudaFuncSetAttribute(kv_partial_tc, cudaFuncAttributeMaxDynamicSharedMemorySize, K2_SMEM);

    convert_all_kernel<<<2048, 256>>>((const float4*)x, (uint2*)xh_p,
                                      (const float4*)W_qkv, (uint2*)wqkvh_p,
                                      (const float4*)W_proj, (uint2*)wprojh_p);

    // K1: qkv = x @ W_qkv (fp16 out), elu+1 fused on q/k columns
    gemm_h<1><<<dim3(QKV_COLS / 128, M_ROWS / 128), 256, SMEM_BYTES>>>(
        xh_p, wqkvh_p, qkvh_p, QKV_COLS, nullptr);

    // K2: kv_ext partials (tensor cores, ones-column ksum) + reduce
    kv_partial_tc<<<dim3(64, NCHUNK), 128, K2_SMEM>>>();
    kv_reduce_kernel<<<dim3(64, 8), 128>>>();

    // K3: normalized readout (tensor cores, fused z via column 64)
    attn_out_tc<<<dim3(SEQ / 64, 64), 128>>>();

    // K4: out = attn @ W_proj + b_proj (fp32 out)
    gemm_h<2><<<dim3(DIM / 128, M_ROWS / 128), 256, SMEM_BYTES>>>(
        attnh_p, wprojh_p, out, DIM, b_proj);
}